// round 2
// baseline (speedup 1.0000x reference)
#include <cuda_runtime.h>
#include <cstddef>

#define B_    8
#define N_    8192
#define M_    2048
#define K_    32
#define CIN   64
#define XPAD  68          // 67 inputs padded to 68 (zero col 67)
#define ROWS  128         // rows per CTA = 4 neighborhoods of K=32

__device__ __forceinline__ float sel4(const float4 v, int kk) {
    return kk == 0 ? v.x : kk == 1 ? v.y : kk == 2 ? v.z : v.w;
}

// C[128,128] += A[128, K4*4] (lda) * W[K4*4, 128]; per-thread 8x8 tile.
template<int K4>
__device__ __forceinline__ void mm(const float* __restrict__ sA, int lda,
                                   const float* __restrict__ sW,
                                   int r0, int o0, float acc[8][8])
{
    const float* pA = sA + r0 * lda;
    #pragma unroll 1
    for (int k0 = 0; k0 < K4 * 4; k0 += 4) {
        float4 a[8];
        #pragma unroll
        for (int i = 0; i < 8; i++)
            a[i] = *(const float4*)(pA + i * lda + k0);
        #pragma unroll
        for (int kk = 0; kk < 4; kk++) {
            float4 w0 = *(const float4*)(sW + (k0 + kk) * 128 + o0);
            float4 w1 = *(const float4*)(sW + (k0 + kk) * 128 + o0 + 4);
            #pragma unroll
            for (int i = 0; i < 8; i++) {
                float av = sel4(a[i], kk);
                acc[i][0] = fmaf(av, w0.x, acc[i][0]);
                acc[i][1] = fmaf(av, w0.y, acc[i][1]);
                acc[i][2] = fmaf(av, w0.z, acc[i][2]);
                acc[i][3] = fmaf(av, w0.w, acc[i][3]);
                acc[i][4] = fmaf(av, w1.x, acc[i][4]);
                acc[i][5] = fmaf(av, w1.y, acc[i][5]);
                acc[i][6] = fmaf(av, w1.z, acc[i][6]);
                acc[i][7] = fmaf(av, w1.w, acc[i][7]);
            }
        }
    }
}

__device__ __forceinline__ void zero_acc(float acc[8][8]) {
    #pragma unroll
    for (int i = 0; i < 8; i++)
        #pragma unroll
        for (int j = 0; j < 8; j++)
            acc[i][j] = 0.f;
}

__device__ __forceinline__ void relu_store(const float acc[8][8],
                                           const float* __restrict__ bias,
                                           int r0, int o0,
                                           float* __restrict__ sC)
{
    float bb[8];
    #pragma unroll
    for (int j = 0; j < 8; j++) bb[j] = bias[o0 + j];
    #pragma unroll
    for (int i = 0; i < 8; i++) {
        float4 v0, v1;
        v0.x = fmaxf(acc[i][0] + bb[0], 0.f);
        v0.y = fmaxf(acc[i][1] + bb[1], 0.f);
        v0.z = fmaxf(acc[i][2] + bb[2], 0.f);
        v0.w = fmaxf(acc[i][3] + bb[3], 0.f);
        v1.x = fmaxf(acc[i][4] + bb[4], 0.f);
        v1.y = fmaxf(acc[i][5] + bb[5], 0.f);
        v1.z = fmaxf(acc[i][6] + bb[6], 0.f);
        v1.w = fmaxf(acc[i][7] + bb[7], 0.f);
        *(float4*)(sC + (r0 + i) * 128 + o0)     = v0;
        *(float4*)(sC + (r0 + i) * 128 + o0 + 4) = v1;
    }
}

__global__ __launch_bounds__(256, 1)
void ps_kernel(const float* __restrict__ xyz, const float* __restrict__ feat,
               const int* __restrict__ nbr, const int* __restrict__ anc,
               const float* __restrict__ W1, const float* __restrict__ b1,
               const float* __restrict__ W2, const float* __restrict__ b2,
               const float* __restrict__ W3, const float* __restrict__ b3,
               float* __restrict__ out)
{
    extern __shared__ float sm[];
    float* sX  = sm;                    // 128 x 68
    float* sH1 = sX  + ROWS * XPAD;     // 128 x 128
    float* sH2 = sH1 + ROWS * 128;      // 128 x 128
    float* sW  = sH2 + ROWS * 128;      // 128 x 128 (weight staging)

    const int tid = threadIdx.x;
    const int ct  = blockIdx.x;
    const int b   = ct >> 9;            // / 512
    const int m0  = (ct & 511) << 2;    // 4 anchors per CTA

    // ---- gather: build X[128, 68] = [rel_xyz(3) | feats(64) | 0] ----
    {
        int r = tid >> 1, h = tid & 1;  // 2 threads per row
        int m = m0 + (r >> 5);
        int k = r & 31;
        int n = nbr[((size_t)(b * M_ + m)) * K_ + k];
        const float* fb = feat + (size_t)b * CIN * N_;
        float* xr = sX + r * XPAD;
        if (h == 0) {
            int a = anc[b * M_ + m];
            const float* xb = xyz + (size_t)b * N_ * 3;
            xr[0] = xb[n * 3 + 0] - xb[a * 3 + 0];
            xr[1] = xb[n * 3 + 1] - xb[a * 3 + 1];
            xr[2] = xb[n * 3 + 2] - xb[a * 3 + 2];
            #pragma unroll
            for (int c = 0; c < 32; c++) xr[3 + c] = __ldg(fb + c * N_ + n);
        } else {
            #pragma unroll
            for (int c = 32; c < 64; c++) xr[3 + c] = __ldg(fb + c * N_ + n);
            xr[67] = 0.f;
        }
    }
    // stage W1 [67,128] -> sW[68,128], zero-padded row 67
    for (int i = tid; i < 68 * 128; i += 256) {
        int r = i >> 7;
        sW[i] = (r < 67) ? W1[i] : 0.f;
    }
    __syncthreads();

    const int ty = tid >> 4, tx = tid & 15;
    const int r0 = ty * 8, o0 = tx * 8;

    float acc[8][8];

    // ---- layer 1: X[128,68] @ W1[68,128] ----
    zero_acc(acc);
    mm<17>(sX, XPAD, sW, r0, o0, acc);
    relu_store(acc, b1, r0, o0, sH1);
    __syncthreads();

    // stage W2
    for (int i = tid; i < 128 * 128; i += 256) sW[i] = W2[i];
    __syncthreads();

    // ---- layer 2: H1[128,128] @ W2[128,128] ----
    zero_acc(acc);
    mm<32>(sH1, 128, sW, r0, o0, acc);
    relu_store(acc, b2, r0, o0, sH2);
    __syncthreads();

    // ---- layer 3 (two 128-col halves) + fused maxpool ----
    float* pmax = sX;  // reuse: [16][128] partial row-maxes
    #pragma unroll 1
    for (int half = 0; half < 2; half++) {
        for (int i = tid; i < 128 * 128; i += 256) {
            int r = i >> 7, c = i & 127;
            sW[i] = W3[r * 256 + half * 128 + c];
        }
        __syncthreads();

        zero_acc(acc);
        mm<32>(sH2, 128, sW, r0, o0, acc);

        float bb[8], mx[8];
        #pragma unroll
        for (int j = 0; j < 8; j++) {
            bb[j] = b3[half * 128 + o0 + j];
            mx[j] = 0.f;  // post-ReLU values are >= 0
        }
        #pragma unroll
        for (int i = 0; i < 8; i++)
            #pragma unroll
            for (int j = 0; j < 8; j++)
                mx[j] = fmaxf(mx[j], fmaxf(acc[i][j] + bb[j], 0.f));
        #pragma unroll
        for (int j = 0; j < 8; j++)
            pmax[ty * 128 + o0 + j] = mx[j];
        __syncthreads();

        // reduce 4 partials per neighborhood, write out [B,256,M]
        for (int p = tid; p < 512; p += 256) {
            int g = p >> 7, c = p & 127;
            float v = fmaxf(fmaxf(pmax[(g * 4 + 0) * 128 + c],
                                  pmax[(g * 4 + 1) * 128 + c]),
                            fmaxf(pmax[(g * 4 + 2) * 128 + c],
                                  pmax[(g * 4 + 3) * 128 + c]));
            out[((size_t)b * 256 + half * 128 + c) * M_ + m0 + g] = v;
        }
        __syncthreads();
    }
}

extern "C" void kernel_launch(void* const* d_in, const int* in_sizes, int n_in,
                              void* d_out, int out_size)
{
    const float* xyz  = (const float*)d_in[0];
    const float* feat = (const float*)d_in[1];
    const int*   nbr  = (const int*)d_in[2];
    const int*   anc  = (const int*)d_in[3];
    const float* W1   = (const float*)d_in[4];
    const float* b1   = (const float*)d_in[5];
    const float* W2   = (const float*)d_in[6];
    const float* b2   = (const float*)d_in[7];
    const float* W3   = (const float*)d_in[8];
    const float* b3   = (const float*)d_in[9];
    float* out = (float*)d_out;

    const int smem = (ROWS * XPAD + 3 * ROWS * 128) * (int)sizeof(float);  // 231424 B
    cudaFuncSetAttribute(ps_kernel, cudaFuncAttributeMaxDynamicSharedMemorySize, smem);
    ps_kernel<<<4096, 256, smem>>>(xyz, feat, nbr, anc, W1, b1, W2, b2, W3, b3, out);
}

// round 4
// speedup vs baseline: 1.8637x; 1.8637x over previous
#include <cuda_runtime.h>
#include <cuda_bf16.h>
#include <cstdint>
#include <cstddef>

#define B_    8
#define N_    8192
#define M_    2048
#define CIN   64
#define AST   136   // sA row stride in bf16 (128 + 8 pad -> conflict-free frags)
#define WST   136   // sW row stride in bf16

// dynamic smem layout (bf16 unless noted):
//   sAhi[128][136], sAlo[128][136]   activations hi/lo
//   sWhi[128][136], sWlo[128][136]   weights (transposed, n-major) hi/lo
//   sBias[512] f32  (b1:0..127, b2:128..255, b3:256..511)
//   pmax[8][128] f32
#define SMEM_BYTES (4 * 128 * 136 * 2 + 512 * 4 + 8 * 128 * 4)

__device__ __forceinline__ void bsplit(float v, __nv_bfloat16& h, __nv_bfloat16& l) {
    h = __float2bfloat16(v);
    l = __float2bfloat16(v - __bfloat162float(h));
}

__device__ __forceinline__ void mma_bf16(float c[4], const uint32_t a[4],
                                         uint32_t b0, uint32_t b1) {
    asm volatile(
        "mma.sync.aligned.m16n8k16.row.col.f32.bf16.bf16.f32 "
        "{%0,%1,%2,%3}, {%4,%5,%6,%7}, {%8,%9}, {%0,%1,%2,%3};"
        : "+f"(c[0]), "+f"(c[1]), "+f"(c[2]), "+f"(c[3])
        : "r"(a[0]), "r"(a[1]), "r"(a[2]), "r"(a[3]), "r"(b0), "r"(b1));
}

// C[128,n128] += A[128,K] * W[K,128] with 3xBF16 compensation.
// Warp computes rows [r0, r0+16) x cols [n0, n0+64).
template<int KSTEPS>
__device__ __forceinline__ void gemm(const __nv_bfloat16* __restrict__ sAhi,
                                     const __nv_bfloat16* __restrict__ sAlo,
                                     const __nv_bfloat16* __restrict__ sWhi,
                                     const __nv_bfloat16* __restrict__ sWlo,
                                     int r0, int n0, int lane, float C[8][4])
{
    #pragma unroll
    for (int j = 0; j < 8; j++)
        #pragma unroll
        for (int x = 0; x < 4; x++) C[j][x] = 0.f;

    const int ra = r0 + (lane >> 2);
    const int kq = (lane & 3) * 2;

    #pragma unroll 1
    for (int ks = 0; ks < KSTEPS; ks++) {
        const int kc = ks * 16 + kq;
        uint32_t ahi[4], alo[4];
        ahi[0] = *(const uint32_t*)(sAhi + (size_t)ra * AST + kc);
        ahi[1] = *(const uint32_t*)(sAhi + (size_t)(ra + 8) * AST + kc);
        ahi[2] = *(const uint32_t*)(sAhi + (size_t)ra * AST + kc + 8);
        ahi[3] = *(const uint32_t*)(sAhi + (size_t)(ra + 8) * AST + kc + 8);
        alo[0] = *(const uint32_t*)(sAlo + (size_t)ra * AST + kc);
        alo[1] = *(const uint32_t*)(sAlo + (size_t)(ra + 8) * AST + kc);
        alo[2] = *(const uint32_t*)(sAlo + (size_t)ra * AST + kc + 8);
        alo[3] = *(const uint32_t*)(sAlo + (size_t)(ra + 8) * AST + kc + 8);
        #pragma unroll
        for (int j = 0; j < 8; j++) {
            const int n = n0 + j * 8 + (lane >> 2);
            uint32_t bh0 = *(const uint32_t*)(sWhi + (size_t)n * WST + kc);
            uint32_t bh1 = *(const uint32_t*)(sWhi + (size_t)n * WST + kc + 8);
            uint32_t bl0 = *(const uint32_t*)(sWlo + (size_t)n * WST + kc);
            uint32_t bl1 = *(const uint32_t*)(sWlo + (size_t)n * WST + kc + 8);
            mma_bf16(C[j], ahi, bh0, bh1);   // hi*hi
            mma_bf16(C[j], ahi, bl0, bl1);   // hi*lo
            mma_bf16(C[j], alo, bh0, bh1);   // lo*hi
        }
    }
}

// bias + relu on C frags, re-split to bf16 hi/lo, store as next layer's A.
// CALLER MUST __syncthreads() between gemm() and this (WAR hazard: paired
// warp with the other n0 half reads the same A rows this warp overwrites).
__device__ __forceinline__ void store_act(const float C[8][4],
                                          const float* __restrict__ bias,
                                          int r0, int n0, int lane,
                                          __nv_bfloat16* __restrict__ sAhi,
                                          __nv_bfloat16* __restrict__ sAlo)
{
    const int ra = r0 + (lane >> 2);
    #pragma unroll
    for (int j = 0; j < 8; j++) {
        const int c0 = n0 + j * 8 + (lane & 3) * 2;
        const float bb0 = bias[c0], bb1 = bias[c0 + 1];
        float v00 = fmaxf(C[j][0] + bb0, 0.f);
        float v01 = fmaxf(C[j][1] + bb1, 0.f);
        float v10 = fmaxf(C[j][2] + bb0, 0.f);
        float v11 = fmaxf(C[j][3] + bb1, 0.f);
        __nv_bfloat16 h, l;
        __nv_bfloat162 hh, ll;
        bsplit(v00, h, l); hh.x = h; ll.x = l;
        bsplit(v01, h, l); hh.y = h; ll.y = l;
        *(__nv_bfloat162*)(sAhi + (size_t)ra * AST + c0) = hh;
        *(__nv_bfloat162*)(sAlo + (size_t)ra * AST + c0) = ll;
        bsplit(v10, h, l); hh.x = h; ll.x = l;
        bsplit(v11, h, l); hh.y = h; ll.y = l;
        *(__nv_bfloat162*)(sAhi + (size_t)(ra + 8) * AST + c0) = hh;
        *(__nv_bfloat162*)(sAlo + (size_t)(ra + 8) * AST + c0) = ll;
    }
}

__global__ __launch_bounds__(512, 1)
void ps_mma(const float* __restrict__ xyz, const float* __restrict__ feat,
            const int* __restrict__ nbr, const int* __restrict__ anc,
            const float* __restrict__ W1, const float* __restrict__ b1,
            const float* __restrict__ W2, const float* __restrict__ b2,
            const float* __restrict__ W3, const float* __restrict__ b3,
            float* __restrict__ out)
{
    extern __shared__ unsigned char smem[];
    __nv_bfloat16* sAhi = (__nv_bfloat16*)smem;
    __nv_bfloat16* sAlo = sAhi + 128 * AST;
    __nv_bfloat16* sWhi = sAlo + 128 * AST;
    __nv_bfloat16* sWlo = sWhi + 128 * WST;
    float* sBias = (float*)(sWlo + 128 * WST);
    float* pmax  = sBias + 512;

    const int tid  = threadIdx.x;
    const int lane = tid & 31;
    const int wid  = tid >> 5;
    const int ct   = blockIdx.x;
    const int b    = ct >> 9;
    const int m0g  = (ct & 511) << 2;   // 4 anchors per CTA

    // ---- stage biases ----
    {
        float v;
        if (tid < 128)      v = b1[tid];
        else if (tid < 256) v = b2[tid - 128];
        else                v = b3[tid - 256];
        sBias[tid] = v;
    }

    // ---- gather X[128 rows][80 cols] = [rel_xyz(3) | feat(64) | zeros] as bf16 hi/lo ----
    {
        const int r = tid >> 2, q = tid & 3;       // 4 threads per row
        const int m = m0g + (r >> 5);
        const int k = r & 31;
        const int n = nbr[(b * M_ + m) * 32 + k];
        const int a = anc[b * M_ + m];
        const float* xb = xyz + (size_t)b * N_ * 3;
        const float* fb = feat + (size_t)b * CIN * N_;
        __nv_bfloat16* ph = sAhi + (size_t)r * AST;
        __nv_bfloat16* pl = sAlo + (size_t)r * AST;
        #pragma unroll 1
        for (int c = q * 20; c < q * 20 + 20; c++) {
            float v;
            if (c < 3)       v = xb[n * 3 + c] - xb[a * 3 + c];
            else if (c < 67) v = __ldg(fb + (size_t)(c - 3) * N_ + n);
            else             v = 0.f;
            __nv_bfloat16 h, l;
            bsplit(v, h, l);
            ph[c] = h; pl[c] = l;
        }
    }

    // ---- stage W1 [67->80 x 128] transposed: sW[n][k] = W1[k][n] ----
    for (int i = tid; i < 80 * 128; i += 512) {
        const int k = i >> 7, n = i & 127;
        const float v = (k < 67) ? W1[k * 128 + n] : 0.f;
        __nv_bfloat16 h, l;
        bsplit(v, h, l);
        sWhi[(size_t)n * WST + k] = h;
        sWlo[(size_t)n * WST + k] = l;
    }
    __syncthreads();

    const int rg = wid & 7;            // row group: rows [16*rg, 16*rg+16)
    const int r0 = rg * 16;
    const int n0 = (wid >> 3) * 64;    // col half: 0 or 64
    float C[8][4];

    // ---- layer 1 ----
    gemm<5>(sAhi, sAlo, sWhi, sWlo, r0, n0, lane, C);
    __syncthreads();   // all reads of X done before any warp overwrites sA
    store_act(C, sBias, r0, n0, lane, sAhi, sAlo);
    __syncthreads();

    // ---- stage W2, layer 2 ----
    for (int i = tid; i < 128 * 128; i += 512) {
        const int k = i >> 7, n = i & 127;
        __nv_bfloat16 h, l;
        bsplit(W2[i], h, l);
        sWhi[(size_t)n * WST + k] = h;
        sWlo[(size_t)n * WST + k] = l;
    }
    __syncthreads();
    gemm<8>(sAhi, sAlo, sWhi, sWlo, r0, n0, lane, C);
    __syncthreads();   // all reads of H1 done before any warp overwrites sA
    store_act(C, sBias + 128, r0, n0, lane, sAhi, sAlo);
    __syncthreads();

    // ---- layer 3 in two 128-col halves, fused neighborhood maxpool ----
    #pragma unroll 1
    for (int h3 = 0; h3 < 2; h3++) {
        for (int i = tid; i < 128 * 128; i += 512) {
            const int k = i >> 7, n = i & 127;
            __nv_bfloat16 h, l;
            bsplit(W3[k * 256 + h3 * 128 + n], h, l);
            sWhi[(size_t)n * WST + k] = h;
            sWlo[(size_t)n * WST + k] = l;
        }
        __syncthreads();

        gemm<8>(sAhi, sAlo, sWhi, sWlo, r0, n0, lane, C);

        // per-warp pool: bias+relu, max over the 16 rows of this warp's fragment
        #pragma unroll
        for (int j = 0; j < 8; j++) {
            const int c0 = n0 + j * 8 + (lane & 3) * 2;
            const float bb0 = sBias[256 + h3 * 128 + c0];
            const float bb1 = sBias[256 + h3 * 128 + c0 + 1];
            float v0 = fmaxf(fmaxf(C[j][0] + bb0, 0.f), fmaxf(C[j][2] + bb0, 0.f));
            float v1 = fmaxf(fmaxf(C[j][1] + bb1, 0.f), fmaxf(C[j][3] + bb1, 0.f));
            #pragma unroll
            for (int s = 4; s < 32; s <<= 1) {
                v0 = fmaxf(v0, __shfl_xor_sync(0xFFFFFFFFu, v0, s));
                v1 = fmaxf(v1, __shfl_xor_sync(0xFFFFFFFFu, v1, s));
            }
            if (lane < 4) {
                pmax[rg * 128 + c0]     = v0;
                pmax[rg * 128 + c0 + 1] = v1;
            }
        }
        __syncthreads();

        // combine the two 16-row groups of each neighborhood, write out [B,256,M]
        {
            const int c = tid >> 2, g = tid & 3;
            const float v = fmaxf(pmax[(2 * g) * 128 + c], pmax[(2 * g + 1) * 128 + c]);
            out[((size_t)b * 256 + h3 * 128 + c) * M_ + m0g + g] = v;
        }
        __syncthreads();
    }
}

extern "C" void kernel_launch(void* const* d_in, const int* in_sizes, int n_in,
                              void* d_out, int out_size)
{
    const float* xyz  = (const float*)d_in[0];
    const float* feat = (const float*)d_in[1];
    const int*   nbr  = (const int*)d_in[2];
    const int*   anc  = (const int*)d_in[3];
    const float* W1   = (const float*)d_in[4];
    const float* b1   = (const float*)d_in[5];
    const float* W2   = (const float*)d_in[6];
    const float* b2   = (const float*)d_in[7];
    const float* W3   = (const float*)d_in[8];
    const float* b3   = (const float*)d_in[9];
    float* out = (float*)d_out;

    cudaFuncSetAttribute(ps_mma, cudaFuncAttributeMaxDynamicSharedMemorySize, SMEM_BYTES);
    ps_mma<<<4096, 512, SMEM_BYTES>>>(xyz, feat, nbr, anc, W1, b1, W2, b2, W3, b3, out);
}

// round 6
// speedup vs baseline: 2.9273x; 1.5707x over previous
#include <cuda_runtime.h>
#include <cuda_bf16.h>
#include <cstdint>
#include <cstddef>

#define B_   8
#define N_   8192
#define M_   2048
#define CIN  64
#define AST  136      // sA row stride (bf16 elems): 272B -> conflict-free frag LDS
#define WST  136

// smem byte offsets
#define OFF_BIAS 0                       // 512 f32
#define OFF_PMAX 2048                    // 8 x 128 f32
#define OFF_AHI  8192                    // 256 x 136 bf16 = 69632 B
#define OFF_ALO  (OFF_AHI + 69632)
#define OFF_WHI  (OFF_ALO + 69632)       // 128 x 136 bf16 = 34816 B
#define OFF_WLO  (OFF_WHI + 34816)
#define SMEM_BYTES (OFF_WLO + 34816)     // 217088

// 16 MB transposed features: featT[b][n][c]
__device__ float g_featT[(size_t)B_ * N_ * CIN];

__device__ __forceinline__ void bsplit(float v, __nv_bfloat16& h, __nv_bfloat16& l) {
    h = __float2bfloat16(v);
    l = __float2bfloat16(v - __bfloat162float(h));
}
__device__ __forceinline__ uint32_t pk(__nv_bfloat16 a, __nv_bfloat16 b) {
    __nv_bfloat162 t(a, b);
    return *(uint32_t*)&t;
}
// split 4 consecutive cols -> one uint2 to hi, one to lo (elemOff % 4 == 0)
__device__ __forceinline__ void store4q(__nv_bfloat16* hiB, __nv_bfloat16* loB,
                                        int elemOff, const float* v) {
    __nv_bfloat16 h0,l0,h1,l1,h2,l2,h3,l3;
    bsplit(v[0], h0, l0); bsplit(v[1], h1, l1);
    bsplit(v[2], h2, l2); bsplit(v[3], h3, l3);
    uint2 hh; hh.x = pk(h0, h1); hh.y = pk(h2, h3);
    uint2 ll; ll.x = pk(l0, l1); ll.y = pk(l2, l3);
    *(uint2*)(hiB + elemOff) = hh;
    *(uint2*)(loB + elemOff) = ll;
}

__device__ __forceinline__ void mma_bf16(float c[4], const uint32_t a[4],
                                         uint32_t b0, uint32_t b1) {
    asm volatile(
        "mma.sync.aligned.m16n8k16.row.col.f32.bf16.bf16.f32 "
        "{%0,%1,%2,%3}, {%4,%5,%6,%7}, {%8,%9}, {%0,%1,%2,%3};"
        : "+f"(c[0]), "+f"(c[1]), "+f"(c[2]), "+f"(c[3])
        : "r"(a[0]), "r"(a[1]), "r"(a[2]), "r"(a[3]), "r"(b0), "r"(b1));
}

// Warp tile m32 x n64, 3-pass bf16 compensation. C[mt][j][4].
template<int KS>
__device__ __forceinline__ void gemm(const __nv_bfloat16* __restrict__ sAhi,
                                     const __nv_bfloat16* __restrict__ sAlo,
                                     const __nv_bfloat16* __restrict__ sWhi,
                                     const __nv_bfloat16* __restrict__ sWlo,
                                     int r0, int n0, int lane, float C[2][8][4])
{
    #pragma unroll
    for (int mt = 0; mt < 2; mt++)
        #pragma unroll
        for (int j = 0; j < 8; j++)
            #pragma unroll
            for (int x = 0; x < 4; x++) C[mt][j][x] = 0.f;

    const int rq = lane >> 2, kq = (lane & 3) * 2;

    #pragma unroll 2
    for (int ks = 0; ks < KS; ks++) {
        const int kc = ks * 16 + kq;
        uint32_t ahi[2][4], alo[2][4];
        #pragma unroll
        for (int mt = 0; mt < 2; mt++) {
            const int ra = r0 + mt * 16 + rq;
            ahi[mt][0] = *(const uint32_t*)(sAhi + ra * AST + kc);
            ahi[mt][1] = *(const uint32_t*)(sAhi + (ra + 8) * AST + kc);
            ahi[mt][2] = *(const uint32_t*)(sAhi + ra * AST + kc + 8);
            ahi[mt][3] = *(const uint32_t*)(sAhi + (ra + 8) * AST + kc + 8);
            alo[mt][0] = *(const uint32_t*)(sAlo + ra * AST + kc);
            alo[mt][1] = *(const uint32_t*)(sAlo + (ra + 8) * AST + kc);
            alo[mt][2] = *(const uint32_t*)(sAlo + ra * AST + kc + 8);
            alo[mt][3] = *(const uint32_t*)(sAlo + (ra + 8) * AST + kc + 8);
        }
        #pragma unroll
        for (int j = 0; j < 8; j++) {
            const int n = n0 + j * 8 + rq;
            uint32_t bh0 = *(const uint32_t*)(sWhi + n * WST + kc);
            uint32_t bh1 = *(const uint32_t*)(sWhi + n * WST + kc + 8);
            uint32_t bl0 = *(const uint32_t*)(sWlo + n * WST + kc);
            uint32_t bl1 = *(const uint32_t*)(sWlo + n * WST + kc + 8);
            mma_bf16(C[0][j], ahi[0], bh0, bh1);
            mma_bf16(C[1][j], ahi[1], bh0, bh1);
            mma_bf16(C[0][j], ahi[0], bl0, bl1);
            mma_bf16(C[1][j], ahi[1], bl0, bl1);
            mma_bf16(C[0][j], alo[0], bh0, bh1);
            mma_bf16(C[1][j], alo[1], bh0, bh1);
        }
    }
}

// bias+relu, re-split to bf16 hi/lo, store as next layer's A (caller syncs first)
__device__ __forceinline__ void epi(const float C[2][8][4], const float* __restrict__ bias,
                                    int r0, int n0, int lane,
                                    __nv_bfloat16* __restrict__ sAhi,
                                    __nv_bfloat16* __restrict__ sAlo)
{
    const int rq = lane >> 2, q2 = (lane & 3) * 2;
    #pragma unroll
    for (int mt = 0; mt < 2; mt++) {
        const int ra = r0 + mt * 16 + rq;
        #pragma unroll
        for (int j = 0; j < 8; j++) {
            const int c0 = n0 + j * 8 + q2;
            const float bb0 = bias[c0], bb1 = bias[c0 + 1];
            float v0 = fmaxf(C[mt][j][0] + bb0, 0.f);
            float v1 = fmaxf(C[mt][j][1] + bb1, 0.f);
            float v2 = fmaxf(C[mt][j][2] + bb0, 0.f);
            float v3 = fmaxf(C[mt][j][3] + bb1, 0.f);
            __nv_bfloat16 h, l; __nv_bfloat162 hh, ll;
            bsplit(v0, h, l); hh.x = h; ll.x = l;
            bsplit(v1, h, l); hh.y = h; ll.y = l;
            *(__nv_bfloat162*)(sAhi + ra * AST + c0) = hh;
            *(__nv_bfloat162*)(sAlo + ra * AST + c0) = ll;
            bsplit(v2, h, l); hh.x = h; ll.x = l;
            bsplit(v3, h, l); hh.y = h; ll.y = l;
            *(__nv_bfloat162*)(sAhi + (ra + 8) * AST + c0) = hh;
            *(__nv_bfloat162*)(sAlo + (ra + 8) * AST + c0) = ll;
        }
    }
}

// stage W[k][coloff+n] (lead dim ld) -> [n][k] hi/lo, zero pad k>=kreal
__device__ __forceinline__ void stageW(const float* __restrict__ W, int ld, int coloff,
                                       int kreal, int ktot,
                                       __nv_bfloat16* __restrict__ wHi,
                                       __nv_bfloat16* __restrict__ wLo, int tid)
{
    const int n = tid & 127;
    const int kg = tid >> 7;            // 4 k-groups
    const int kspan = ktot >> 2;        // 20 or 32 (mult of 4)
    #pragma unroll 1
    for (int k0 = kg * kspan; k0 < (kg + 1) * kspan; k0 += 4) {
        float v[4];
        #pragma unroll
        for (int j = 0; j < 4; j++) {
            const int k = k0 + j;
            v[j] = (k < kreal) ? __ldg(W + (size_t)k * ld + coloff + n) : 0.f;
        }
        store4q(wHi, wLo, n * WST + k0, v);
    }
}

// ---------------- feature transpose [C][N] -> [N][C] ----------------
__global__ __launch_bounds__(256) void tr_kernel(const float* __restrict__ feat) {
    __shared__ float t[64][65];
    const int b  = blockIdx.x >> 7;
    const int n0 = (blockIdx.x & 127) << 6;
    const int tid = threadIdx.x;
    const float* fb = feat + (size_t)b * CIN * N_;
    for (int i = tid; i < 64 * 64; i += 256) {
        int c = i >> 6, nj = i & 63;
        t[c][nj] = fb[(size_t)c * N_ + n0 + nj];
    }
    __syncthreads();
    const int nj = tid >> 2, cq = (tid & 3) * 16;
    float* drow = g_featT + ((size_t)b * N_ + n0 + nj) * CIN + cq;
    #pragma unroll
    for (int q = 0; q < 16; q += 4) {
        float4 v = make_float4(t[cq + q][nj], t[cq + q + 1][nj],
                               t[cq + q + 2][nj], t[cq + q + 3][nj]);
        *(float4*)(drow + q) = v;
    }
}

// ---------------- main fused kernel: 256 rows (8 neighborhoods) per CTA ----------------
__global__ __launch_bounds__(512, 1)
void ps_mma2(const float* __restrict__ xyz, const float* __restrict__ feat,
             const int* __restrict__ nbr, const int* __restrict__ anc,
             const float* __restrict__ W1, const float* __restrict__ b1,
             const float* __restrict__ W2, const float* __restrict__ b2,
             const float* __restrict__ W3, const float* __restrict__ b3,
             float* __restrict__ out)
{
    extern __shared__ char smem[];
    float* bias = (float*)(smem + OFF_BIAS);
    float* pmax = (float*)(smem + OFF_PMAX);
    __nv_bfloat16* sAhi = (__nv_bfloat16*)(smem + OFF_AHI);
    __nv_bfloat16* sAlo = (__nv_bfloat16*)(smem + OFF_ALO);
    __nv_bfloat16* sWhi = (__nv_bfloat16*)(smem + OFF_WHI);
    __nv_bfloat16* sWlo = (__nv_bfloat16*)(smem + OFF_WLO);

    const int tid = threadIdx.x, lane = tid & 31, w = tid >> 5;
    const int ct = blockIdx.x, b = ct >> 8;
    const int m0 = (ct & 255) << 3;        // 8 anchors per CTA

    bias[tid] = (tid < 128) ? b1[tid] : (tid < 256) ? b2[tid - 128] : b3[tid - 256];

    // ---- gather: rows [256][80] = [rel_xyz(3)|feat(64)|0..], 2 threads/row ----
    {
        const int r = tid >> 1, h = tid & 1;
        const int m = m0 + (r >> 5), k = r & 31;
        const int n = nbr[(b * M_ + m) * 32 + k];
        const int a = anc[b * M_ + m];
        const float* xb = xyz + (size_t)b * N_ * 3;
        const float* ft = g_featT + ((size_t)b * N_ + n) * CIN;
        float xr[3];
        if (h == 0) {
            xr[0] = xb[n * 3 + 0] - xb[a * 3 + 0];
            xr[1] = xb[n * 3 + 1] - xb[a * 3 + 1];
            xr[2] = xb[n * 3 + 2] - xb[a * 3 + 2];
        }
        #pragma unroll 1
        for (int cb = h * 4; cb < 80; cb += 8) {
            float v[4];
            #pragma unroll
            for (int j = 0; j < 4; j++) {
                const int c = cb + j;
                v[j] = (c < 3) ? xr[c] : (c < 67) ? __ldg(ft + (c - 3)) : 0.f;
            }
            store4q(sAhi, sAlo, r * AST + cb, v);
        }
    }
    stageW(W1, 128, 0, 67, 80, sWhi, sWlo, tid);
    __syncthreads();

    const int rg = w & 7;               // row group / neighborhood
    const int r0 = rg * 32;
    const int n0 = (w >> 3) * 64;       // col half
    float C[2][8][4];

    // ---- layer 1: [256,80] @ [80,128] ----
    gemm<5>(sAhi, sAlo, sWhi, sWlo, r0, n0, lane, C);
    __syncthreads();
    epi(C, bias, r0, n0, lane, sAhi, sAlo);
    stageW(W2, 128, 0, 128, 128, sWhi, sWlo, tid);
    __syncthreads();

    // ---- layer 2: [256,128] @ [128,128] ----
    gemm<8>(sAhi, sAlo, sWhi, sWlo, r0, n0, lane, C);
    __syncthreads();
    epi(C, bias + 128, r0, n0, lane, sAhi, sAlo);
    stageW(W3, 256, 0, 128, 128, sWhi, sWlo, tid);
    __syncthreads();

    // ---- layer 3 (two 128-col halves) + fused maxpool ----
    #pragma unroll 1
    for (int h3 = 0; h3 < 2; h3++) {
        gemm<8>(sAhi, sAlo, sWhi, sWlo, r0, n0, lane, C);

        const int q2 = (lane & 3) * 2;
        #pragma unroll
        for (int j = 0; j < 8; j++) {
            const int c0 = n0 + j * 8 + q2;     // 0..127 within half
            const float bb0 = bias[256 + h3 * 128 + c0];
            const float bb1 = bias[256 + h3 * 128 + c0 + 1];
            float v0 = fmaxf(fmaxf(C[0][j][0], C[0][j][2]),
                             fmaxf(C[1][j][0], C[1][j][2]));
            float v1 = fmaxf(fmaxf(C[0][j][1], C[0][j][3]),
                             fmaxf(C[1][j][1], C[1][j][3]));
            v0 = fmaxf(v0 + bb0, 0.f);
            v1 = fmaxf(v1 + bb1, 0.f);
            #pragma unroll
            for (int s = 4; s < 32; s <<= 1) {
                v0 = fmaxf(v0, __shfl_xor_sync(0xFFFFFFFFu, v0, s));
                v1 = fmaxf(v1, __shfl_xor_sync(0xFFFFFFFFu, v1, s));
            }
            if (lane < 4) {
                pmax[rg * 128 + c0]     = v0;
                pmax[rg * 128 + c0 + 1] = v1;
            }
        }
        __syncthreads();

        // coalesced out write: 8 consecutive m per col
        if (tid < 128) {
            const int col = tid;
            float f[8];
            #pragma unroll
            for (int g = 0; g < 8; g++) f[g] = pmax[g * 128 + col];
            const size_t base = ((size_t)(b * 256 + h3 * 128 + col)) * M_ + m0;
            *(float4*)(out + base)     = make_float4(f[0], f[1], f[2], f[3]);
            *(float4*)(out + base + 4) = make_float4(f[4], f[5], f[6], f[7]);
        }
        if (h3 == 0)
            stageW(W3, 256, 128, 128, 128, sWhi, sWlo, tid);
        __syncthreads();
    }
}

extern "C" void kernel_launch(void* const* d_in, const int* in_sizes, int n_in,
                              void* d_out, int out_size)
{
    const float* xyz  = (const float*)d_in[0];
    const float* feat = (const float*)d_in[1];
    const int*   nbr  = (const int*)d_in[2];
    const int*   anc  = (const int*)d_in[3];
    const float* W1   = (const float*)d_in[4];
    const float* b1   = (const float*)d_in[5];
    const float* W2   = (const float*)d_in[6];
    const float* b2   = (const float*)d_in[7];
    const float* W3   = (const float*)d_in[8];
    const float* b3   = (const float*)d_in[9];
    float* out = (float*)d_out;

    tr_kernel<<<B_ * (N_ / 64), 256>>>(feat);
    cudaFuncSetAttribute(ps_mma2, cudaFuncAttributeMaxDynamicSharedMemorySize, SMEM_BYTES);
    ps_mma2<<<2048, 512, SMEM_BYTES>>>(xyz, feat, nbr, anc, W1, b1, W2, b2, W3, b3, out);
}